// round 1
// baseline (speedup 1.0000x reference)
#include <cuda_runtime.h>
#include <math.h>

// Problem constants
#define TT 256
#define BB 128
#define EE 512
#define HH 1024
#define G3 3072   // 3*H

// ---------------------------------------------------------------------------
// Scratch (device globals; zero-init bss — no dynamic allocation anywhere)
// ---------------------------------------------------------------------------
__device__ float g_GI0[(size_t)TT * BB * G3];  // precomputed x @ W_ih0^T + b_ih0
__device__ float g_h0[2][BB * HH];             // layer0 hidden, ping-pong by t parity
__device__ float g_h1[2][BB * HH];             // layer1 hidden
__device__ float g_x1[2][BB * HH];             // layer0 output (layer1 input), by t parity

// ---------------------------------------------------------------------------
// Zero initial hidden states (h in buffer [0] at t=0)
// ---------------------------------------------------------------------------
__global__ void zero_h_kernel() {
    int idx = blockIdx.x * blockDim.x + threadIdx.x;   // 128*256 = 32768 = BB*HH/4
    float4 z = make_float4(0.f, 0.f, 0.f, 0.f);
    ((float4*)g_h0[0])[idx] = z;
    ((float4*)g_h1[0])[idx] = z;
}

// ---------------------------------------------------------------------------
// Precompute GI0[t,b,:] = x[t,b,:] @ W_ih0^T + b_ih0  (skips inactive tiles)
// Tile: 64 (rows within one t) x 64 (gate cols), K=512.  256 threads, 4x4/thread.
// ---------------------------------------------------------------------------
__global__ __launch_bounds__(256) void gi0_kernel(
    const float* __restrict__ x, const float* __restrict__ W,
    const float* __restrict__ bias, const int* __restrict__ bs)
{
    __shared__ __align__(16) float As[32][68];  // [k][m]
    __shared__ __align__(16) float Bs[32][68];  // [k][n]

    const int nbase = blockIdx.x * 64;
    const int trow  = blockIdx.y;          // 0..511
    const int t     = trow >> 1;
    const int mb    = (trow & 1) << 6;     // 0 or 64
    if (mb >= bs[t]) return;               // packed-seq: rows never used downstream

    const int tid = threadIdx.x;
    const int tx  = tid & 15;              // m-group
    const int ty  = tid >> 4;              // n-group

    float acc[4][4];
#pragma unroll
    for (int i = 0; i < 4; i++)
#pragma unroll
        for (int j = 0; j < 4; j++) acc[i][j] = 0.f;

    const float* Arow = x + (size_t)(t * BB + mb) * EE;

    for (int k0 = 0; k0 < EE; k0 += 32) {
#pragma unroll
        for (int r = 0; r < 2; r++) {
            int idx = tid + r * 256;
            int m = idx >> 3, c4 = (idx & 7) * 4;
            float4 v = *(const float4*)&Arow[(size_t)m * EE + k0 + c4];
            As[c4 + 0][m] = v.x; As[c4 + 1][m] = v.y;
            As[c4 + 2][m] = v.z; As[c4 + 3][m] = v.w;
        }
#pragma unroll
        for (int r = 0; r < 2; r++) {
            int idx = tid + r * 256;
            int n = idx >> 3, c4 = (idx & 7) * 4;
            float4 v = *(const float4*)&W[(size_t)(nbase + n) * EE + k0 + c4];
            Bs[c4 + 0][n] = v.x; Bs[c4 + 1][n] = v.y;
            Bs[c4 + 2][n] = v.z; Bs[c4 + 3][n] = v.w;
        }
        __syncthreads();
#pragma unroll
        for (int k = 0; k < 32; k++) {
            float4 a = *(const float4*)&As[k][tx * 4];
            float4 b = *(const float4*)&Bs[k][ty * 4];
            const float* ap = (const float*)&a;
            const float* bp = (const float*)&b;
#pragma unroll
            for (int i = 0; i < 4; i++)
#pragma unroll
                for (int j = 0; j < 4; j++)
                    acc[i][j] = fmaf(ap[i], bp[j], acc[i][j]);
        }
        __syncthreads();
    }

    const int n = nbase + ty * 4;
    float4 bv = *(const float4*)&bias[n];
#pragma unroll
    for (int i = 0; i < 4; i++) {
        int m = tx * 4 + i;
        size_t row = (size_t)(t * BB + mb + m);
        float4 o;
        o.x = acc[i][0] + bv.x; o.y = acc[i][1] + bv.y;
        o.z = acc[i][2] + bv.z; o.w = acc[i][3] + bv.w;
        *(float4*)&g_GI0[row * G3 + n] = o;
    }
}

// ---------------------------------------------------------------------------
// Per (k4, acc) micro-MMA: 4 k-steps, 2 m x 2 j x 3 gates
// ---------------------------------------------------------------------------
__device__ __forceinline__ void mma_micro(const float* __restrict__ ws,
                                          const float (*sm)[66],
                                          int k4, int lane, int jl,
                                          float acc[2][2][3])
{
    float2 a[4];
#pragma unroll
    for (int i = 0; i < 4; i++)
        a[i] = *(const float2*)&sm[k4 + i][2 * lane];
#pragma unroll
    for (int ji = 0; ji < 2; ji++) {
#pragma unroll
        for (int g = 0; g < 3; g++) {
            float4 w = *(const float4*)&ws[(g * 16 + jl + ji) * 32 + k4];
            const float* wp = (const float*)&w;
#pragma unroll
            for (int i = 0; i < 4; i++) {
                acc[0][ji][g] = fmaf(a[i].x, wp[i], acc[0][ji][g]);
                acc[1][ji][g] = fmaf(a[i].y, wp[i], acc[1][ji][g]);
            }
        }
    }
}

__device__ __forceinline__ float sigf(float v) {
    return 1.f / (1.f + __expf(-v));
}

// ---------------------------------------------------------------------------
// Fused pipelined step: blocks [0,128) do layer0 @ t=k; blocks [128,256) do
// layer1 @ t=k-1 (inputs of layer1@t-1 were produced by the previous kernel).
// Each CTA: 64 rows x 16 hidden cols x 3 gates; inactive tiles copy h through.
// ---------------------------------------------------------------------------
__global__ __launch_bounds__(256) void fused_step(
    const float* __restrict__ Whh0, const float* __restrict__ Wih1,
    const float* __restrict__ Whh1,
    const float* __restrict__ bhh0, const float* __restrict__ bih1,
    const float* __restrict__ bhh1,
    const int* __restrict__ bs, int kk)
{
    __shared__ __align__(16) float hs[32][66];
    __shared__ __align__(16) float xs[32][66];
    __shared__ __align__(16) float ws_h[48 * 32];
    __shared__ __align__(16) float ws_i[48 * 32];

    const int c  = blockIdx.x;
    const bool l1 = (c >= 128);
    const int t  = l1 ? (kk - 1) : kk;
    if (t < 0 || t >= TT) return;

    const int cc    = l1 ? (c - 128) : c;
    const int jbase = (cc >> 1) * 16;
    const int mbase = (cc & 1) << 6;
    const int active = bs[t];
    const int p = t & 1;

    const float* hold = l1 ? g_h0[0] /*placeholder*/ : g_h0[0];
    hold = l1 ? g_h1[p] : g_h0[p];
    float* hnew = l1 ? g_h1[p ^ 1] : g_h0[p ^ 1];

    const int tid = threadIdx.x;

    if (mbase >= active) {
        // inactive tile: h passes through unchanged into the ping-pong buffer
        int m  = tid >> 2;
        int j4 = tid & 3;
        const float4* src = (const float4*)(hold + (size_t)(mbase + m) * HH + jbase);
        float4* dst = (float4*)(hnew + (size_t)(mbase + m) * HH + jbase);
        dst[j4] = src[j4];
        return;
    }

    const int lane = tid & 31;
    const int warp = tid >> 5;
    const int jl   = 2 * warp;           // local j base (0..14)

    float acch[2][2][3];
    float acci[2][2][3];
#pragma unroll
    for (int a = 0; a < 2; a++)
#pragma unroll
        for (int b = 0; b < 2; b++)
#pragma unroll
            for (int g = 0; g < 3; g++) { acch[a][b][g] = 0.f; acci[a][b][g] = 0.f; }

    const float* Wh = l1 ? Whh1 : Whh0;
    const float* Ai = g_x1[p];           // used only when l1

    for (int k0 = 0; k0 < HH; k0 += 32) {
        // h tile (64 m x 32 k), stored transposed [k][m]
#pragma unroll
        for (int r = 0; r < 2; r++) {
            int idx = tid + r * 256;
            int m = idx >> 3, c4 = (idx & 7) * 4;
            float4 v = *(const float4*)&hold[(size_t)(mbase + m) * HH + k0 + c4];
            hs[c4 + 0][m] = v.x; hs[c4 + 1][m] = v.y;
            hs[c4 + 2][m] = v.z; hs[c4 + 3][m] = v.w;
        }
        // W_hh tile: 48 gate-rows x 32 k
#pragma unroll
        for (int base = 0; base < 384; base += 256) {
            int idx = tid + base;
            if (idx < 384) {
                int r = idx >> 3, c4 = (idx & 7) * 4;
                int grow = jbase + (r & 15) + (r >> 4) * HH;
                *(float4*)&ws_h[r * 32 + c4] =
                    *(const float4*)&Wh[(size_t)grow * HH + k0 + c4];
            }
        }
        if (l1) {
#pragma unroll
            for (int r = 0; r < 2; r++) {
                int idx = tid + r * 256;
                int m = idx >> 3, c4 = (idx & 7) * 4;
                float4 v = *(const float4*)&Ai[(size_t)(mbase + m) * HH + k0 + c4];
                xs[c4 + 0][m] = v.x; xs[c4 + 1][m] = v.y;
                xs[c4 + 2][m] = v.z; xs[c4 + 3][m] = v.w;
            }
#pragma unroll
            for (int base = 0; base < 384; base += 256) {
                int idx = tid + base;
                if (idx < 384) {
                    int r = idx >> 3, c4 = (idx & 7) * 4;
                    int grow = jbase + (r & 15) + (r >> 4) * HH;
                    *(float4*)&ws_i[r * 32 + c4] =
                        *(const float4*)&Wih1[(size_t)grow * HH + k0 + c4];
                }
            }
        }
        __syncthreads();

        if (l1) {
#pragma unroll 4
            for (int k4 = 0; k4 < 32; k4 += 4) {
                mma_micro(ws_h, hs, k4, lane, jl, acch);
                mma_micro(ws_i, xs, k4, lane, jl, acci);
            }
        } else {
#pragma unroll 4
            for (int k4 = 0; k4 < 32; k4 += 4) {
                mma_micro(ws_h, hs, k4, lane, jl, acch);
            }
        }
        __syncthreads();
    }

    // ---- gate math + state update ----
    const float* bh = l1 ? bhh1 : bhh0;
#pragma unroll
    for (int mi = 0; mi < 2; mi++) {
        int m = mbase + 2 * lane + mi;
#pragma unroll
        for (int ji = 0; ji < 2; ji++) {
            int j = jbase + jl + ji;
            float gr, gz, gn;
            if (!l1) {
                const float* gi = g_GI0 + (size_t)(t * BB + m) * G3;
                gr = gi[j]; gz = gi[HH + j]; gn = gi[2 * HH + j];
            } else {
                gr = acci[mi][ji][0] + bih1[j];
                gz = acci[mi][ji][1] + bih1[HH + j];
                gn = acci[mi][ji][2] + bih1[2 * HH + j];
            }
            float hr  = acch[mi][ji][0] + bh[j];
            float hz  = acch[mi][ji][1] + bh[HH + j];
            float hnn = acch[mi][ji][2] + bh[2 * HH + j];

            float r  = sigf(gr + hr);
            float z  = sigf(gz + hz);
            float nv = tanhf(fmaf(r, hnn, gn));
            float hp = hold[(size_t)m * HH + j];
            float hv = fmaf(z, hp - nv, nv);          // (1-z)*n + z*h

            hnew[(size_t)m * HH + j] = (m < active) ? hv : hp;
            if (!l1) g_x1[p][(size_t)m * HH + j] = hv; // layer1 input is UNMASKED hn
        }
    }
}

// ---------------------------------------------------------------------------
// Final gather: out[l, b, :] = h_l[unsorted_indices[b], :]
// ---------------------------------------------------------------------------
__global__ void gather_kernel(const int* __restrict__ u, float* __restrict__ out) {
    int idx = blockIdx.x * blockDim.x + threadIdx.x;  // 2*128*256 float4 = 65536
    int l   = idx / (BB * (HH / 4));
    int rem = idx % (BB * (HH / 4));
    int b   = rem / (HH / 4);
    int j4  = rem % (HH / 4);
    const float* src = (l ? g_h1[0] : g_h0[0]) + (size_t)u[b] * HH;
    ((float4*)out)[idx] = ((const float4*)src)[j4];
}

// ---------------------------------------------------------------------------
extern "C" void kernel_launch(void* const* d_in, const int* in_sizes, int n_in,
                              void* d_out, int out_size) {
    const float* x    = (const float*)d_in[0];
    const float* Wih0 = (const float*)d_in[1];
    const float* Whh0 = (const float*)d_in[2];
    const float* bih0 = (const float*)d_in[3];
    // d_in[4] = b_hh0
    const float* bhh0 = (const float*)d_in[4];
    const float* Wih1 = (const float*)d_in[5];
    const float* Whh1 = (const float*)d_in[6];
    const float* bih1 = (const float*)d_in[7];
    const float* bhh1 = (const float*)d_in[8];
    const int*   bs   = (const int*)d_in[9];
    const int*   ui   = (const int*)d_in[10];

    zero_h_kernel<<<128, 256>>>();
    gi0_kernel<<<dim3(48, 2 * TT), 256>>>(x, Wih0, bih0, bs);
    for (int k = 0; k <= TT; k++)
        fused_step<<<256, 256>>>(Whh0, Wih1, Whh1, bhh0, bih1, bhh1, bs, k);
    gather_kernel<<<256, 256>>>(ui, (float*)d_out);
}

// round 2
// speedup vs baseline: 1.0017x; 1.0017x over previous
#include <cuda_runtime.h>
#include <math.h>

// Problem constants
#define TT 256
#define BB 128
#define EE 512
#define HH 1024
#define G3 3072   // 3*H

// ---------------------------------------------------------------------------
// Scratch (device globals; zero-init bss — no dynamic allocation anywhere)
// ---------------------------------------------------------------------------
__device__ float g_GI0[(size_t)TT * BB * G3];  // precomputed x @ W_ih0^T + b_ih0
__device__ float g_h0[2][BB * HH];             // layer0 hidden, ping-pong by t parity
__device__ float g_h1[2][BB * HH];             // layer1 hidden
__device__ float g_x1[2][BB * HH];             // layer0 output (layer1 input), by t parity

// ---------------------------------------------------------------------------
// Zero initial hidden states (h in buffer [0] at t=0)
// ---------------------------------------------------------------------------
__global__ void zero_h_kernel() {
    int idx = blockIdx.x * blockDim.x + threadIdx.x;   // 128*256 = 32768 = BB*HH/4
    float4 z = make_float4(0.f, 0.f, 0.f, 0.f);
    ((float4*)g_h0[0])[idx] = z;
    ((float4*)g_h1[0])[idx] = z;
}

// ---------------------------------------------------------------------------
// Precompute GI0[t,b,:] = x[t,b,:] @ W_ih0^T + b_ih0  (skips inactive tiles)
// Tile: 64 (rows within one t) x 64 (gate cols), K=512.  256 threads, 4x4/thread.
// ---------------------------------------------------------------------------
__global__ __launch_bounds__(256) void gi0_kernel(
    const float* __restrict__ x, const float* __restrict__ W,
    const float* __restrict__ bias, const int* __restrict__ bs)
{
    __shared__ __align__(16) float As[32][68];  // [k][m]
    __shared__ __align__(16) float Bs[32][68];  // [k][n]

    const int nbase = blockIdx.x * 64;
    const int trow  = blockIdx.y;          // 0..511
    const int t     = trow >> 1;
    const int mb    = (trow & 1) << 6;     // 0 or 64
    if (mb >= bs[t]) return;               // packed-seq: rows never used downstream

    const int tid = threadIdx.x;
    const int tx  = tid & 15;              // m-group
    const int ty  = tid >> 4;              // n-group

    float acc[4][4];
#pragma unroll
    for (int i = 0; i < 4; i++)
#pragma unroll
        for (int j = 0; j < 4; j++) acc[i][j] = 0.f;

    const float* Arow = x + (size_t)(t * BB + mb) * EE;

    for (int k0 = 0; k0 < EE; k0 += 32) {
#pragma unroll
        for (int r = 0; r < 2; r++) {
            int idx = tid + r * 256;
            int m = idx >> 3, c4 = (idx & 7) * 4;
            float4 v = *(const float4*)&Arow[(size_t)m * EE + k0 + c4];
            As[c4 + 0][m] = v.x; As[c4 + 1][m] = v.y;
            As[c4 + 2][m] = v.z; As[c4 + 3][m] = v.w;
        }
#pragma unroll
        for (int r = 0; r < 2; r++) {
            int idx = tid + r * 256;
            int n = idx >> 3, c4 = (idx & 7) * 4;
            float4 v = *(const float4*)&W[(size_t)(nbase + n) * EE + k0 + c4];
            Bs[c4 + 0][n] = v.x; Bs[c4 + 1][n] = v.y;
            Bs[c4 + 2][n] = v.z; Bs[c4 + 3][n] = v.w;
        }
        __syncthreads();
#pragma unroll
        for (int k = 0; k < 32; k++) {
            float4 a = *(const float4*)&As[k][tx * 4];
            float4 b = *(const float4*)&Bs[k][ty * 4];
            const float* ap = (const float*)&a;
            const float* bp = (const float*)&b;
#pragma unroll
            for (int i = 0; i < 4; i++)
#pragma unroll
                for (int j = 0; j < 4; j++)
                    acc[i][j] = fmaf(ap[i], bp[j], acc[i][j]);
        }
        __syncthreads();
    }

    const int n = nbase + ty * 4;
    float4 bv = *(const float4*)&bias[n];
#pragma unroll
    for (int i = 0; i < 4; i++) {
        int m = tx * 4 + i;
        size_t row = (size_t)(t * BB + mb + m);
        float4 o;
        o.x = acc[i][0] + bv.x; o.y = acc[i][1] + bv.y;
        o.z = acc[i][2] + bv.z; o.w = acc[i][3] + bv.w;
        *(float4*)&g_GI0[row * G3 + n] = o;
    }
}

// ---------------------------------------------------------------------------
// Per (k4, acc) micro-MMA: 4 k-steps, 2 m x 2 j x 3 gates
// ---------------------------------------------------------------------------
__device__ __forceinline__ void mma_micro(const float* __restrict__ ws,
                                          const float (*sm)[66],
                                          int k4, int lane, int jl,
                                          float acc[2][2][3])
{
    float2 a[4];
#pragma unroll
    for (int i = 0; i < 4; i++)
        a[i] = *(const float2*)&sm[k4 + i][2 * lane];
#pragma unroll
    for (int ji = 0; ji < 2; ji++) {
#pragma unroll
        for (int g = 0; g < 3; g++) {
            float4 w = *(const float4*)&ws[(g * 16 + jl + ji) * 32 + k4];
            const float* wp = (const float*)&w;
#pragma unroll
            for (int i = 0; i < 4; i++) {
                acc[0][ji][g] = fmaf(a[i].x, wp[i], acc[0][ji][g]);
                acc[1][ji][g] = fmaf(a[i].y, wp[i], acc[1][ji][g]);
            }
        }
    }
}

__device__ __forceinline__ float sigf(float v) {
    return 1.f / (1.f + __expf(-v));
}

// ---------------------------------------------------------------------------
// Fused pipelined step: blocks [0,128) do layer0 @ t=k; blocks [128,256) do
// layer1 @ t=k-1 (inputs of layer1@t-1 were produced by the previous kernel).
// Each CTA: 64 rows x 16 hidden cols x 3 gates; inactive tiles copy h through.
// ---------------------------------------------------------------------------
__global__ __launch_bounds__(256) void fused_step(
    const float* __restrict__ Whh0, const float* __restrict__ Wih1,
    const float* __restrict__ Whh1,
    const float* __restrict__ bhh0, const float* __restrict__ bih1,
    const float* __restrict__ bhh1,
    const int* __restrict__ bs, int kk)
{
    __shared__ __align__(16) float hs[32][66];
    __shared__ __align__(16) float xs[32][66];
    __shared__ __align__(16) float ws_h[48 * 32];
    __shared__ __align__(16) float ws_i[48 * 32];

    const int c  = blockIdx.x;
    const bool l1 = (c >= 128);
    const int t  = l1 ? (kk - 1) : kk;
    if (t < 0 || t >= TT) return;

    const int cc    = l1 ? (c - 128) : c;
    const int jbase = (cc >> 1) * 16;
    const int mbase = (cc & 1) << 6;
    const int active = bs[t];
    const int p = t & 1;

    const float* hold = l1 ? g_h0[0] /*placeholder*/ : g_h0[0];
    hold = l1 ? g_h1[p] : g_h0[p];
    float* hnew = l1 ? g_h1[p ^ 1] : g_h0[p ^ 1];

    const int tid = threadIdx.x;

    if (mbase >= active) {
        // inactive tile: h passes through unchanged into the ping-pong buffer
        int m  = tid >> 2;
        int j4 = tid & 3;
        const float4* src = (const float4*)(hold + (size_t)(mbase + m) * HH + jbase);
        float4* dst = (float4*)(hnew + (size_t)(mbase + m) * HH + jbase);
        dst[j4] = src[j4];
        return;
    }

    const int lane = tid & 31;
    const int warp = tid >> 5;
    const int jl   = 2 * warp;           // local j base (0..14)

    float acch[2][2][3];
    float acci[2][2][3];
#pragma unroll
    for (int a = 0; a < 2; a++)
#pragma unroll
        for (int b = 0; b < 2; b++)
#pragma unroll
            for (int g = 0; g < 3; g++) { acch[a][b][g] = 0.f; acci[a][b][g] = 0.f; }

    const float* Wh = l1 ? Whh1 : Whh0;
    const float* Ai = g_x1[p];           // used only when l1

    for (int k0 = 0; k0 < HH; k0 += 32) {
        // h tile (64 m x 32 k), stored transposed [k][m]
#pragma unroll
        for (int r = 0; r < 2; r++) {
            int idx = tid + r * 256;
            int m = idx >> 3, c4 = (idx & 7) * 4;
            float4 v = *(const float4*)&hold[(size_t)(mbase + m) * HH + k0 + c4];
            hs[c4 + 0][m] = v.x; hs[c4 + 1][m] = v.y;
            hs[c4 + 2][m] = v.z; hs[c4 + 3][m] = v.w;
        }
        // W_hh tile: 48 gate-rows x 32 k
#pragma unroll
        for (int base = 0; base < 384; base += 256) {
            int idx = tid + base;
            if (idx < 384) {
                int r = idx >> 3, c4 = (idx & 7) * 4;
                int grow = jbase + (r & 15) + (r >> 4) * HH;
                *(float4*)&ws_h[r * 32 + c4] =
                    *(const float4*)&Wh[(size_t)grow * HH + k0 + c4];
            }
        }
        if (l1) {
#pragma unroll
            for (int r = 0; r < 2; r++) {
                int idx = tid + r * 256;
                int m = idx >> 3, c4 = (idx & 7) * 4;
                float4 v = *(const float4*)&Ai[(size_t)(mbase + m) * HH + k0 + c4];
                xs[c4 + 0][m] = v.x; xs[c4 + 1][m] = v.y;
                xs[c4 + 2][m] = v.z; xs[c4 + 3][m] = v.w;
            }
#pragma unroll
            for (int base = 0; base < 384; base += 256) {
                int idx = tid + base;
                if (idx < 384) {
                    int r = idx >> 3, c4 = (idx & 7) * 4;
                    int grow = jbase + (r & 15) + (r >> 4) * HH;
                    *(float4*)&ws_i[r * 32 + c4] =
                        *(const float4*)&Wih1[(size_t)grow * HH + k0 + c4];
                }
            }
        }
        __syncthreads();

        if (l1) {
#pragma unroll 4
            for (int k4 = 0; k4 < 32; k4 += 4) {
                mma_micro(ws_h, hs, k4, lane, jl, acch);
                mma_micro(ws_i, xs, k4, lane, jl, acci);
            }
        } else {
#pragma unroll 4
            for (int k4 = 0; k4 < 32; k4 += 4) {
                mma_micro(ws_h, hs, k4, lane, jl, acch);
            }
        }
        __syncthreads();
    }

    // ---- gate math + state update ----
    const float* bh = l1 ? bhh1 : bhh0;
#pragma unroll
    for (int mi = 0; mi < 2; mi++) {
        int m = mbase + 2 * lane + mi;
#pragma unroll
        for (int ji = 0; ji < 2; ji++) {
            int j = jbase + jl + ji;
            float gr, gz, gn;
            if (!l1) {
                const float* gi = g_GI0 + (size_t)(t * BB + m) * G3;
                gr = gi[j]; gz = gi[HH + j]; gn = gi[2 * HH + j];
            } else {
                gr = acci[mi][ji][0] + bih1[j];
                gz = acci[mi][ji][1] + bih1[HH + j];
                gn = acci[mi][ji][2] + bih1[2 * HH + j];
            }
            float hr  = acch[mi][ji][0] + bh[j];
            float hz  = acch[mi][ji][1] + bh[HH + j];
            float hnn = acch[mi][ji][2] + bh[2 * HH + j];

            float r  = sigf(gr + hr);
            float z  = sigf(gz + hz);
            float nv = tanhf(fmaf(r, hnn, gn));
            float hp = hold[(size_t)m * HH + j];
            float hv = fmaf(z, hp - nv, nv);          // (1-z)*n + z*h

            hnew[(size_t)m * HH + j] = (m < active) ? hv : hp;
            if (!l1) g_x1[p][(size_t)m * HH + j] = hv; // layer1 input is UNMASKED hn
        }
    }
}

// ---------------------------------------------------------------------------
// Final gather: out[l, b, :] = h_l[unsorted_indices[b], :]
// ---------------------------------------------------------------------------
__global__ void gather_kernel(const int* __restrict__ u, float* __restrict__ out) {
    int idx = blockIdx.x * blockDim.x + threadIdx.x;  // 2*128*256 float4 = 65536
    int l   = idx / (BB * (HH / 4));
    int rem = idx % (BB * (HH / 4));
    int b   = rem / (HH / 4);
    int j4  = rem % (HH / 4);
    const float* src = (l ? g_h1[0] : g_h0[0]) + (size_t)u[b] * HH;
    ((float4*)out)[idx] = ((const float4*)src)[j4];
}

// ---------------------------------------------------------------------------
extern "C" void kernel_launch(void* const* d_in, const int* in_sizes, int n_in,
                              void* d_out, int out_size) {
    const float* x    = (const float*)d_in[0];
    const float* Wih0 = (const float*)d_in[1];
    const float* Whh0 = (const float*)d_in[2];
    const float* bih0 = (const float*)d_in[3];
    // d_in[4] = b_hh0
    const float* bhh0 = (const float*)d_in[4];
    const float* Wih1 = (const float*)d_in[5];
    const float* Whh1 = (const float*)d_in[6];
    const float* bih1 = (const float*)d_in[7];
    const float* bhh1 = (const float*)d_in[8];
    const int*   bs   = (const int*)d_in[9];
    const int*   ui   = (const int*)d_in[10];

    zero_h_kernel<<<128, 256>>>();
    gi0_kernel<<<dim3(48, 2 * TT), 256>>>(x, Wih0, bih0, bs);
    for (int k = 0; k <= TT; k++)
        fused_step<<<256, 256>>>(Whh0, Wih1, Whh1, bhh0, bih1, bhh1, bs, k);
    gather_kernel<<<256, 256>>>(ui, (float*)d_out);
}